// round 15
// baseline (speedup 1.0000x reference)
#include <cuda_runtime.h>
#include <cuda_bf16.h>
#include <math.h>
#include <stdint.h>

#define B_   16
#define N_   32768
#define S_   256
#define H_   256
#define NH_  8
#define DH_  32
#define DFF_ 1024
#define NC_  13

// pre-split transposed weight pool offsets (uint32 elements)
#define OFF_QKV 0
#define OFF_OUT 196608
#define OFF_FF1 262144
#define OFF_FF2 524288
#define OFF_H1  786432
#define W_TOTAL 819200

// ---------------- scratch (device globals; no allocations allowed) ----------
__device__ float g_sumxyz[B_*S_*3];
__device__ float g_sumfeat[B_*S_*4];
__device__ float g_cnt[B_*S_];
__device__ int   g_assign[B_*N_];
__device__ float g_x[B_*S_*H_];
__device__ float g_qkv[B_*S_*3*H_];
__device__ float g_attn[B_*S_*H_];
__device__ float g_tmp[B_*S_*H_];
__device__ float g_ff[B_*S_*DFF_];
__device__ float g_h1[B_*S_*H_];
__device__ float g_logits[B_*S_*NC_];
__device__ uint32_t g_Whi[W_TOTAL];
__device__ uint32_t g_Wlo[W_TOTAL];

// ---------------- utils ----------
__device__ __forceinline__ float gelu_exact(float x) {
    return 0.5f * x * (1.0f + erff(x * 0.70710678118654752440f));
}

// split a float2 into packed bf16x2 hi and lo: x = hi + lo + O(2^-18 x)
__device__ __forceinline__ void bf16_split2(float fx, float fy,
                                            uint32_t& hi, uint32_t& lo) {
    __nv_bfloat162 h = __float22bfloat162_rn(make_float2(fx, fy));
    hi = *(uint32_t*)&h;
    float2 hf = __bfloat1622float2(h);
    __nv_bfloat162 l = __float22bfloat162_rn(make_float2(fx - hf.x, fy - hf.y));
    lo = *(uint32_t*)&l;
}

__device__ __forceinline__ void mma_bf16(float* d, const uint32_t* a,
                                         uint32_t b0, uint32_t b1) {
    asm volatile(
        "mma.sync.aligned.m16n8k16.row.col.f32.bf16.bf16.f32 "
        "{%0,%1,%2,%3},{%4,%5,%6,%7},{%8,%9},{%0,%1,%2,%3};"
        : "+f"(d[0]), "+f"(d[1]), "+f"(d[2]), "+f"(d[3])
        : "r"(a[0]), "r"(a[1]), "r"(a[2]), "r"(a[3]), "r"(b0), "r"(b1));
}

// ---------------- merged weight split + transpose + accumulator zero -------
// W[N][K] -> hi/lo [K/2][N] per layer, 5 regions dispatched by global id.
__global__ void split_all_kernel(const float* __restrict__ qkv_w,
                                 const float* __restrict__ out_w,
                                 const float* __restrict__ ff1_w,
                                 const float* __restrict__ ff2_w,
                                 const float* __restrict__ h1_w) {
    int id = blockIdx.x * blockDim.x + threadIdx.x;
    if (id < B_*S_*3) g_sumxyz[id]  = 0.f;
    if (id < B_*S_*4) g_sumfeat[id] = 0.f;
    if (id < B_*S_)   g_cnt[id]     = 0.f;
    if (id >= W_TOTAL) return;
    const float* src; int Nw, Kp, off, lsS, lsD, rel;
    if (id < 262144) {
        if (id < 196608) { src=qkv_w; Nw=768;  Kp=128; off=OFF_QKV; lsS=196608; lsD=98304;  rel=id; }
        else             { src=out_w; Nw=256;  Kp=128; off=OFF_OUT; lsS=65536;  lsD=32768;  rel=id-196608; }
    } else if (id < 524288) {
        src=ff1_w; Nw=1024; Kp=128; off=OFF_FF1; lsS=262144; lsD=131072; rel=id-262144;
    } else if (id < 786432) {
        src=ff2_w; Nw=256;  Kp=512; off=OFF_FF2; lsS=262144; lsD=131072; rel=id-524288;
    } else {
        src=h1_w;  Nw=256;  Kp=128; off=OFF_H1;  lsS=0;      lsD=0;      rel=id-786432;
    }
    int l   = rel / (Kp * Nw);
    int r2  = rel - l * (Kp * Nw);
    int n   = r2 / Kp;
    int kp  = r2 - n * Kp;
    const float* s = src + (size_t)l*lsS + (size_t)n*(2*Kp) + 2*kp;
    uint32_t h, lw;
    bf16_split2(s[0], s[1], h, lw);
    size_t d = (size_t)off + (size_t)l*lsD + (size_t)kp*Nw + n;
    g_Whi[d] = h;
    g_Wlo[d] = lw;
}

// ---------------- point -> seed argmin + block-local segment sums ----------
__global__ void assign_kernel(const float* __restrict__ xyz,
                              const float* __restrict__ feat,
                              const int*   __restrict__ seed_idx) {
    __shared__ float4 s_seed[S_];
    __shared__ float s_acc[S_*8];
    int b     = blockIdx.x >> 4;
    int chunk = blockIdx.x & 15;
    int tid   = threadIdx.x;

    {
        int idx = seed_idx[tid];
        float a0 = xyz[(size_t)(b*N_ + idx)*3 + 0];
        float a1 = xyz[(size_t)(b*N_ + idx)*3 + 1];
        float a2 = xyz[(size_t)(b*N_ + idx)*3 + 2];
        s_seed[tid] = make_float4(a0, a1, a2, (a0*a0 + a1*a1) + a2*a2);
    }
    #pragma unroll
    for (int i = 0; i < 8; i++) s_acc[tid + i*256] = 0.f;
    __syncthreads();

    for (int pp = 0; pp < 2; pp++) {
        int n0 = chunk*2048 + pp*1024;
        float px[4], py[4], pz[4], pw[4];
        #pragma unroll
        for (int i = 0; i < 4; i++) {
            size_t off = (size_t)(b*N_ + n0 + i*256 + tid);
            px[i] = xyz[off*3+0];
            py[i] = xyz[off*3+1];
            pz[i] = xyz[off*3+2];
            pw[i] = (px[i]*px[i] + py[i]*py[i]) + pz[i]*pz[i];
        }
        float best[4] = {INFINITY, INFINITY, INFINITY, INFINITY};
        int   bi[4]   = {0, 0, 0, 0};
        #pragma unroll 2
        for (int s = 0; s < S_; s++) {
            float4 sd = s_seed[s];
            #pragma unroll
            for (int i = 0; i < 4; i++) {
                float d = px[i] * sd.x;
                d = fmaf(py[i], sd.y, d);
                d = fmaf(pz[i], sd.z, d);
                float d2 = (pw[i] + sd.w) - 2.0f*d;
                if (d2 < best[i]) { best[i] = d2; bi[i] = s; }  // first wins
            }
        }
        #pragma unroll
        for (int i = 0; i < 4; i++) {
            size_t off = (size_t)(b*N_ + n0 + i*256 + tid);
            g_assign[off] = bi[i];
            float4 f = ((const float4*)feat)[off];
            float* a = &s_acc[bi[i]*8];
            atomicAdd(a+0, px[i]); atomicAdd(a+1, py[i]); atomicAdd(a+2, pz[i]);
            atomicAdd(a+3, f.x);   atomicAdd(a+4, f.y);
            atomicAdd(a+5, f.z);   atomicAdd(a+6, f.w);
            atomicAdd(a+7, 1.0f);
        }
    }
    __syncthreads();

    int s  = tid;
    int bs = b*S_ + s;
    atomicAdd(&g_sumxyz [bs*3+0], s_acc[s*8+0]);
    atomicAdd(&g_sumxyz [bs*3+1], s_acc[s*8+1]);
    atomicAdd(&g_sumxyz [bs*3+2], s_acc[s*8+2]);
    atomicAdd(&g_sumfeat[bs*4+0], s_acc[s*8+3]);
    atomicAdd(&g_sumfeat[bs*4+1], s_acc[s*8+4]);
    atomicAdd(&g_sumfeat[bs*4+2], s_acc[s*8+5]);
    atomicAdd(&g_sumfeat[bs*4+3], s_acc[s*8+6]);
    atomicAdd(&g_cnt[bs],         s_acc[s*8+7]);
}

// ---------------- superpoint features -> token projection ----------
// 512 blocks x 8 rows: sp vectors computed in parallel (thread (r,c) -> one
// element), one barrier, then each thread emits its channel for all 8 rows.
__global__ void tokens_kernel(const float* __restrict__ xyz,
                              const int*   __restrict__ seed_idx,
                              const float* __restrict__ pw,
                              const float* __restrict__ pb) {
    __shared__ float sp[8][8];
    int tid = threadIdx.x;
    int blk = blockIdx.x;            // 0..511
    if (tid < 64) {
        int r = tid >> 3, c = tid & 7;
        if (c < 7) {
            int bs = blk*8 + r;
            int b = bs >> 8, s = bs & 255;
            float cnt   = g_cnt[bs];
            float denom = fmaxf(cnt, 1.0f);
            bool  empty = (cnt == 0.0f);
            float v;
            if (c < 3) {
                int idx = seed_idx[s];
                float seedc = xyz[(size_t)(b*N_ + idx)*3 + c];
                v = empty ? seedc : g_sumxyz[bs*3 + c] / denom;
            } else {
                v = empty ? 0.f : g_sumfeat[bs*4 + (c - 3)] / denom;
            }
            sp[r][c] = v;
        }
    }
    float w[7];
    #pragma unroll
    for (int i = 0; i < 7; i++) w[i] = pw[tid*7 + i];
    float bb = pb[tid];
    __syncthreads();
    #pragma unroll
    for (int r = 0; r < 8; r++) {
        float acc = 0.f;
        #pragma unroll
        for (int i = 0; i < 7; i++) acc = fmaf(sp[r][i], w[i], acc);
        g_x[(size_t)(blk*8 + r)*H_ + tid] = acc + bb;
    }
}

// ---------------- tensor-core GEMM (3xBF16, m16n8k16): C = epi(A@Wt + b) ---
// A: fp32, split in-kernel. W: PRE-SPLIT transposed bf16 hi/lo [K/2][Nw].
// 3 passes: al*bh + ah*bl + ah*bh (dropped lo*lo ~2^-18).
// KT=16, double-buffered, +8 pad => conflict-free fragment LDS.
// EPI: 0 = none, 1 = gelu, 2 = +residual
template<int TM, int TN, int WM, int WN, int THREADS, int MINCTA, int EPI>
__global__ void __launch_bounds__(THREADS, MINCTA)
sgemm_tc(const float* __restrict__ A,
         const uint32_t* __restrict__ Whi, const uint32_t* __restrict__ Wlo,
         const float* __restrict__ bias, const float* __restrict__ res,
         float* __restrict__ C, int M, int N, int K, int Nw) {
    constexpr int KT = 16;
    constexpr int PA = TM + 8;
    constexpr int PB = TN + 8;
    constexpr int WCOLS = TN / WN;
    constexpr int MT = WM / 16;
    constexpr int NT = WN / 8;
    constexpr int NLA = TM * 4 / THREADS;   // A float4 loads per thread
    constexpr int WU  = TN * 2 / THREADS;   // W uint4 loads per thread per array
    constexpr int C4  = TN / 4;             // uint4 per kpair row

    __shared__ __align__(16) uint32_t As_hi[2][8][PA];
    __shared__ __align__(16) uint32_t As_lo[2][8][PA];
    __shared__ __align__(16) uint32_t Ws_hi[2][8][PB];
    __shared__ __align__(16) uint32_t Ws_lo[2][8][PB];

    const int tid  = threadIdx.x;
    const int lane = tid & 31;
    const int wid  = tid >> 5;
    const int wrow = wid / WCOLS;
    const int wcol = wid % WCOLS;
    const int gr   = lane >> 2;          // 0..7
    const int ct   = lane & 3;           // 0..3
    const int bm   = blockIdx.y * TM;
    const int bn   = blockIdx.x * TN;

    float acc[MT][NT][4];
    #pragma unroll
    for (int mt = 0; mt < MT; mt++)
        #pragma unroll
        for (int nt = 0; nt < NT; nt++)
            #pragma unroll
            for (int j = 0; j < 4; j++) acc[mt][nt][j] = 0.f;

    float4 av[NLA];
    uint4  wh[WU], wl[WU];

    #pragma unroll
    for (int t = 0; t < NLA; t++) {
        int id = tid + t*THREADS, r = id >> 2, kq = id & 3;
        av[t] = *(const float4*)(A + (size_t)(bm + r)*K + kq*4);
    }
    #pragma unroll
    for (int t = 0; t < WU; t++) {
        int u = tid + t*THREADS, kp = u / C4, c4 = u % C4;
        size_t base = (size_t)kp*Nw + bn + c4*4;
        wh[t] = *(const uint4*)(Whi + base);
        wl[t] = *(const uint4*)(Wlo + base);
    }

    auto stage = [&](int buf) {
        #pragma unroll
        for (int t = 0; t < NLA; t++) {
            int id = tid + t*THREADS, r = id >> 2, kq = id & 3;
            uint32_t h0, l0, h1, l1;
            bf16_split2(av[t].x, av[t].y, h0, l0);
            bf16_split2(av[t].z, av[t].w, h1, l1);
            As_hi[buf][2*kq  ][r] = h0;
            As_hi[buf][2*kq+1][r] = h1;
            As_lo[buf][2*kq  ][r] = l0;
            As_lo[buf][2*kq+1][r] = l1;
        }
        #pragma unroll
        for (int t = 0; t < WU; t++) {
            int u = tid + t*THREADS, kp = u / C4, c4 = u % C4;
            *(uint4*)&Ws_hi[buf][kp][c4*4] = wh[t];
            *(uint4*)&Ws_lo[buf][kp][c4*4] = wl[t];
        }
    };

    stage(0);
    __syncthreads();

    const int nk = K / KT;
    for (int kt = 0; kt < nk; kt++) {
        const int buf = kt & 1;
        if (kt + 1 < nk) {
            int k0 = (kt + 1) * KT;
            #pragma unroll
            for (int t = 0; t < NLA; t++) {
                int id = tid + t*THREADS, r = id >> 2, kq = id & 3;
                av[t] = *(const float4*)(A + (size_t)(bm + r)*K + k0 + kq*4);
            }
            int kp0 = (kt + 1) * 8;
            #pragma unroll
            for (int t = 0; t < WU; t++) {
                int u = tid + t*THREADS, kp = u / C4, c4 = u % C4;
                size_t base = (size_t)(kp0 + kp)*Nw + bn + c4*4;
                wh[t] = *(const uint4*)(Whi + base);
                wl[t] = *(const uint4*)(Wlo + base);
            }
        }

        uint32_t ah[MT][4], al[MT][4];
        #pragma unroll
        for (int mt = 0; mt < MT; mt++) {
            int m = wrow*WM + mt*16 + gr;
            ah[mt][0] = As_hi[buf][ct  ][m];
            ah[mt][1] = As_hi[buf][ct  ][m + 8];
            ah[mt][2] = As_hi[buf][ct+4][m];
            ah[mt][3] = As_hi[buf][ct+4][m + 8];
            al[mt][0] = As_lo[buf][ct  ][m];
            al[mt][1] = As_lo[buf][ct  ][m + 8];
            al[mt][2] = As_lo[buf][ct+4][m];
            al[mt][3] = As_lo[buf][ct+4][m + 8];
        }
        #pragma unroll
        for (int nt = 0; nt < NT; nt++) {
            int n = wcol*WN + nt*8 + gr;
            uint32_t bh0 = Ws_hi[buf][ct  ][n];
            uint32_t bh1 = Ws_hi[buf][ct+4][n];
            uint32_t bl0 = Ws_lo[buf][ct  ][n];
            uint32_t bl1 = Ws_lo[buf][ct+4][n];
            #pragma unroll
            for (int mt = 0; mt < MT; mt++) {
                mma_bf16(acc[mt][nt], al[mt], bh0, bh1);   // lo*hi
                mma_bf16(acc[mt][nt], ah[mt], bl0, bl1);   // hi*lo
                mma_bf16(acc[mt][nt], ah[mt], bh0, bh1);   // hi*hi
            }
        }

        if (kt + 1 < nk) stage(buf ^ 1);
        __syncthreads();
    }

    // epilogue: C-frag m16n8: c0,c1 at (gr, ct*2..+1), c2,c3 at (gr+8, same)
    #pragma unroll
    for (int mt = 0; mt < MT; mt++) {
        int row = bm + wrow*WM + mt*16 + gr;
        #pragma unroll
        for (int nt = 0; nt < NT; nt++) {
            int col = bn + wcol*WN + nt*8 + ct*2;
            float b0 = bias[col], b1 = bias[col + 1];
            float c0 = acc[mt][nt][0] + b0;
            float c1 = acc[mt][nt][1] + b1;
            float c2 = acc[mt][nt][2] + b0;
            float c3 = acc[mt][nt][3] + b1;
            if (EPI == 1) {
                c0 = gelu_exact(c0); c1 = gelu_exact(c1);
                c2 = gelu_exact(c2); c3 = gelu_exact(c3);
            }
            if (EPI == 2) {
                float2 r0 = *(const float2*)(res + (size_t)row*N + col);
                float2 r1 = *(const float2*)(res + (size_t)(row + 8)*N + col);
                c0 += r0.x; c1 += r0.y; c2 += r1.x; c3 += r1.y;
            }
            *(float2*)(C + (size_t)row*N + col)       = make_float2(c0, c1);
            *(float2*)(C + (size_t)(row + 8)*N + col) = make_float2(c2, c3);
        }
    }
}

// ---------------- attention: 4-way key split with in-warp tree merge --------
// grid = B*NH*4 (query quarters), 256 threads. Thread quad (lanes ks=0..3 of
// the same query) covers disjoint 64-key quarters; partial online-softmax
// states merge via shfl_xor(1) then shfl_xor(2) (partners always in-warp).
__global__ void attention_kernel(const float* __restrict__ qkv,
                                 float* __restrict__ outp) {
    __shared__ float Ks[S_][DH_];
    int bid  = blockIdx.x;
    int qq   = bid & 3;                     // query quarter
    int bh   = bid >> 2;
    int b    = bh >> 3, h = bh & 7;
    int tid  = threadIdx.x;                 // 0..255
    const float* base = qkv + (size_t)b*S_*(3*H_);
    {
        const float4* kr = (const float4*)(base + (size_t)tid*(3*H_) + H_ + h*DH_);
        float4* dst = (float4*)&Ks[tid][0];
        #pragma unroll
        for (int i = 0; i < DH_/4; i++) dst[i] = kr[i];
    }
    int qlocal = tid >> 2;                  // 0..63
    int ks     = tid & 3;                   // key quarter
    int qrow   = qq*64 + qlocal;
    float q[DH_];
    {
        const float4* qr = (const float4*)(base + (size_t)qrow*(3*H_) + h*DH_);
        #pragma unroll
        for (int i = 0; i < DH_/4; i++) ((float4*)q)[i] = qr[i];
    }
    __syncthreads();

    const float scale = 0.17677669529663688110f;   // 1/sqrt(32)
    float m = -INFINITY, l = 0.f;
    float acc[DH_];
    #pragma unroll
    for (int d = 0; d < DH_; d++) acc[d] = 0.f;
    const float* vbase = base + 2*H_ + h*DH_;
    const int j0 = ks * 64;

    for (int jj = 0; jj < 64; jj += 2) {
        int j = j0 + jj;
        float d0 = 0.f, d1 = 0.f, d2 = 0.f, d3 = 0.f;
        float e0 = 0.f, e1 = 0.f, e2 = 0.f, e3 = 0.f;
        #pragma unroll
        for (int i = 0; i < DH_/4; i++) {
            float4 k0 = ((const float4*)&Ks[j][0])[i];
            float4 k1 = ((const float4*)&Ks[j+1][0])[i];
            d0 = fmaf(q[4*i+0], k0.x, d0);
            d1 = fmaf(q[4*i+1], k0.y, d1);
            d2 = fmaf(q[4*i+2], k0.z, d2);
            d3 = fmaf(q[4*i+3], k0.w, d3);
            e0 = fmaf(q[4*i+0], k1.x, e0);
            e1 = fmaf(q[4*i+1], k1.y, e1);
            e2 = fmaf(q[4*i+2], k1.z, e2);
            e3 = fmaf(q[4*i+3], k1.w, e3);
        }
        float s0 = ((d0 + d1) + (d2 + d3)) * scale;
        float s1 = ((e0 + e1) + (e2 + e3)) * scale;
        float mn = fmaxf(m, fmaxf(s0, s1));
        float c  = __expf(m - mn);
        float p0 = __expf(s0 - mn);
        float p1 = __expf(s1 - mn);
        l = l*c + p0 + p1;
        const float4* v0 = (const float4*)(vbase + (size_t)j*(3*H_));
        const float4* v1 = (const float4*)(vbase + (size_t)(j+1)*(3*H_));
        #pragma unroll
        for (int i = 0; i < DH_/4; i++) {
            float4 a = v0[i], bq = v1[i];
            acc[i*4+0] = fmaf(acc[i*4+0], c, fmaf(p0, a.x, p1*bq.x));
            acc[i*4+1] = fmaf(acc[i*4+1], c, fmaf(p0, a.y, p1*bq.y));
            acc[i*4+2] = fmaf(acc[i*4+2], c, fmaf(p0, a.z, p1*bq.z));
            acc[i*4+3] = fmaf(acc[i*4+3], c, fmaf(p0, a.w, p1*bq.w));
        }
        m = mn;
    }

    // tree-merge partial softmax states across the thread quad
    #pragma unroll
    for (int o = 1; o <= 2; o <<= 1) {
        float mo = __shfl_xor_sync(0xffffffffu, m, o);
        float lo = __shfl_xor_sync(0xffffffffu, l, o);
        float mn = fmaxf(m, mo);
        float c1 = __expf(m  - mn);
        float c2 = __expf(mo - mn);
        l = l*c1 + lo*c2;
        #pragma unroll
        for (int d = 0; d < DH_; d++) {
            float ao = __shfl_xor_sync(0xffffffffu, acc[d], o);
            acc[d] = acc[d]*c1 + ao*c2;
        }
        m = mn;
    }
    float inv = 1.0f / l;
    // all 4 lanes hold the full result; each writes its 8-channel slice
    float* orow = outp + (size_t)(b*S_ + qrow)*H_ + h*DH_ + ks*8;
    float4 w0, w1;
    w0.x = acc[ks*8+0]*inv; w0.y = acc[ks*8+1]*inv;
    w0.z = acc[ks*8+2]*inv; w0.w = acc[ks*8+3]*inv;
    w1.x = acc[ks*8+4]*inv; w1.y = acc[ks*8+5]*inv;
    w1.z = acc[ks*8+6]*inv; w1.w = acc[ks*8+7]*inv;
    ((float4*)orow)[0] = w0;
    ((float4*)orow)[1] = w1;
}

// ---------------- layernorm: warp-per-row, barrier-free ----------
__global__ void layernorm_kernel(const float* __restrict__ in,
                                 const float* __restrict__ gw,
                                 const float* __restrict__ gb,
                                 float* __restrict__ outp) {
    int warp = threadIdx.x >> 5;
    int lane = threadIdx.x & 31;
    int row  = blockIdx.x * 8 + warp;
    const float4* in4 = (const float4*)in;
    float4 a = in4[(size_t)row*64 + lane*2];
    float4 b = in4[(size_t)row*64 + lane*2 + 1];
    float s1 = ((a.x + a.y) + (a.z + a.w)) + ((b.x + b.y) + (b.z + b.w));
    float s2 = ((a.x*a.x + a.y*a.y) + (a.z*a.z + a.w*a.w))
             + ((b.x*b.x + b.y*b.y) + (b.z*b.z + b.w*b.w));
    #pragma unroll
    for (int o = 16; o > 0; o >>= 1) {
        s1 += __shfl_xor_sync(0xffffffffu, s1, o);
        s2 += __shfl_xor_sync(0xffffffffu, s2, o);
    }
    float mean = s1 * (1.0f/H_);
    float var  = s2 * (1.0f/H_) - mean*mean;
    float rstd = rsqrtf(var + 1e-5f);
    float4 g0 = ((const float4*)gw)[lane*2];
    float4 g1 = ((const float4*)gw)[lane*2 + 1];
    float4 o0 = ((const float4*)gb)[lane*2];
    float4 o1 = ((const float4*)gb)[lane*2 + 1];
    float4 r0, r1;
    r0.x = (a.x - mean)*rstd*g0.x + o0.x;
    r0.y = (a.y - mean)*rstd*g0.y + o0.y;
    r0.z = (a.z - mean)*rstd*g0.z + o0.z;
    r0.w = (a.w - mean)*rstd*g0.w + o0.w;
    r1.x = (b.x - mean)*rstd*g1.x + o1.x;
    r1.y = (b.y - mean)*rstd*g1.y + o1.y;
    r1.z = (b.z - mean)*rstd*g1.z + o1.z;
    r1.w = (b.w - mean)*rstd*g1.w + o1.w;
    ((float4*)outp)[(size_t)row*64 + lane*2]     = r0;
    ((float4*)outp)[(size_t)row*64 + lane*2 + 1] = r1;
}

// ---------------- head2: logits (M x 13), one thread per output ----------
__global__ void head2_kernel(const float* __restrict__ X,
                             const float* __restrict__ W,
                             const float* __restrict__ bias) {
    int t = blockIdx.x * blockDim.x + threadIdx.x;
    if (t >= B_*S_*NC_) return;
    int row = t / NC_, c = t - row*NC_;
    const float4* x = (const float4*)(X + (size_t)row*H_);
    const float4* w = (const float4*)(W + (size_t)c*H_);
    float s0 = 0.f, s1 = 0.f, s2 = 0.f, s3 = 0.f;
    #pragma unroll 8
    for (int k = 0; k < H_/4; k++) {
        float4 xv = x[k], wv = w[k];
        s0 = fmaf(xv.x, wv.x, s0); s1 = fmaf(xv.y, wv.y, s1);
        s2 = fmaf(xv.z, wv.z, s2); s3 = fmaf(xv.w, wv.w, s3);
    }
    g_logits[t] = (s0+s1) + (s2+s3) + bias[c];
}

// ---------------- final gather to point logits ----------
__global__ void gather_kernel(float* __restrict__ out) {
    int t = blockIdx.x * blockDim.x + threadIdx.x;
    if (t >= B_*N_*NC_) return;
    int r = t / NC_;
    int c = t - r*NC_;
    int b = r >> 15;                // r / N_
    int a = g_assign[r];
    out[t] = g_logits[(b*S_ + a)*NC_ + c];
}

// ---------------- host launcher ----------
extern "C" void kernel_launch(void* const* d_in, const int* in_sizes, int n_in,
                              void* d_out, int out_size) {
    const float* xyz      = (const float*)d_in[0];
    const float* feat     = (const float*)d_in[1];
    const int*   seed_idx = (const int*)  d_in[2];
    const float* proj_w   = (const float*)d_in[3];
    const float* proj_b   = (const float*)d_in[4];
    const float* qkv_w    = (const float*)d_in[5];
    const float* qkv_b    = (const float*)d_in[6];
    const float* out_w    = (const float*)d_in[7];
    const float* out_b    = (const float*)d_in[8];
    const float* ln1_g    = (const float*)d_in[9];
    const float* ln1_b    = (const float*)d_in[10];
    const float* ln2_g    = (const float*)d_in[11];
    const float* ln2_b    = (const float*)d_in[12];
    const float* ff1_w    = (const float*)d_in[13];
    const float* ff1_b    = (const float*)d_in[14];
    const float* ff2_w    = (const float*)d_in[15];
    const float* ff2_b    = (const float*)d_in[16];
    const float* hln_g    = (const float*)d_in[17];
    const float* hln_b    = (const float*)d_in[18];
    const float* h1_w     = (const float*)d_in[19];
    const float* h1_b     = (const float*)d_in[20];
    const float* h2_w     = (const float*)d_in[21];
    const float* h2_b     = (const float*)d_in[22];
    float* out = (float*)d_out;

    float *p_x, *p_qkv, *p_attn, *p_tmp, *p_ff, *p_h1;
    uint32_t *p_Whi, *p_Wlo;
    cudaGetSymbolAddress((void**)&p_x,    g_x);
    cudaGetSymbolAddress((void**)&p_qkv,  g_qkv);
    cudaGetSymbolAddress((void**)&p_attn, g_attn);
    cudaGetSymbolAddress((void**)&p_tmp,  g_tmp);
    cudaGetSymbolAddress((void**)&p_ff,   g_ff);
    cudaGetSymbolAddress((void**)&p_h1,   g_h1);
    cudaGetSymbolAddress((void**)&p_Whi,  g_Whi);
    cudaGetSymbolAddress((void**)&p_Wlo,  g_Wlo);

    const int M = B_*S_;   // 4096

    split_all_kernel<<<(W_TOTAL + 255)/256, 256>>>(qkv_w, out_w, ff1_w,
                                                   ff2_w, h1_w);
    assign_kernel<<<B_*16, 256>>>(xyz, feat, seed_idx);
    tokens_kernel<<<M/8, 256>>>(xyz, seed_idx, proj_w, proj_b);

    for (int l = 0; l < 2; l++) {
        // QKV: M=4096, N=768, K=256 -> 64x128 tiles, grid 6x64=384
        sgemm_tc<64,128,64,32,128,4,0><<<dim3(3*H_/128, M/64), 128>>>(
            p_x, p_Whi+OFF_QKV + l*98304, p_Wlo+OFF_QKV + l*98304,
            qkv_b + l*3*H_, nullptr, p_qkv, M, 3*H_, H_, 768);
        attention_kernel<<<B_*NH_*4, 256>>>(p_qkv, p_attn);
        // out-proj: N=256, K=256 -> 64x64 tiles, grid 4x64=256, +residual
        sgemm_tc<64,64,32,32,128,4,2><<<dim3(H_/64, M/64), 128>>>(
            p_attn, p_Whi+OFF_OUT + l*32768, p_Wlo+OFF_OUT + l*32768,
            out_b + l*H_, p_x, p_tmp, M, H_, H_, 256);
        layernorm_kernel<<<M/8, 256>>>(p_tmp, ln1_g + l*H_, ln1_b + l*H_, p_x);
        // FF1: N=1024, K=256 -> 64x128 tiles, grid 8x64=512, gelu
        sgemm_tc<64,128,64,32,128,4,1><<<dim3(DFF_/128, M/64), 128>>>(
            p_x, p_Whi+OFF_FF1 + l*131072, p_Wlo+OFF_FF1 + l*131072,
            ff1_b + l*DFF_, nullptr, p_ff, M, DFF_, H_, 1024);
        // FF2: N=256, K=1024 -> 64x64 tiles, +residual
        sgemm_tc<64,64,32,32,128,4,2><<<dim3(H_/64, M/64), 128>>>(
            p_ff, p_Whi+OFF_FF2 + l*131072, p_Wlo+OFF_FF2 + l*131072,
            ff2_b + l*H_, p_x, p_tmp, M, H_, DFF_, 256);
        layernorm_kernel<<<M/8, 256>>>(p_tmp, ln2_g + l*H_, ln2_b + l*H_, p_x);
    }

    layernorm_kernel<<<M/8, 256>>>(p_x, hln_g, hln_b, p_tmp);
    sgemm_tc<64,64,32,32,128,4,1><<<dim3(H_/64, M/64), 128>>>(
        p_tmp, p_Whi+OFF_H1, p_Wlo+OFF_H1, h1_b, nullptr, p_h1,
        M, H_, H_, 256);
    head2_kernel<<<(M*NC_ + 255)/256, 256>>>(p_h1, h2_w, h2_b);
    gather_kernel<<<(B_*N_*NC_ + 255)/256, 256>>>(out);
}

// round 16
// speedup vs baseline: 1.5229x; 1.5229x over previous
#include <cuda_runtime.h>
#include <cuda_bf16.h>
#include <math.h>
#include <stdint.h>

#define B_   16
#define N_   32768
#define S_   256
#define H_   256
#define NH_  8
#define DH_  32
#define DFF_ 1024
#define NC_  13

// pre-split transposed weight pool offsets (uint32 elements)
#define OFF_QKV 0
#define OFF_OUT 196608
#define OFF_FF1 262144
#define OFF_FF2 524288
#define OFF_H1  786432
#define W_TOTAL 819200

// ---------------- scratch (device globals; no allocations allowed) ----------
__device__ float g_sumxyz[B_*S_*3];
__device__ float g_sumfeat[B_*S_*4];
__device__ float g_cnt[B_*S_];
__device__ int   g_assign[B_*N_];
__device__ float g_x[B_*S_*H_];
__device__ float g_qkv[B_*S_*3*H_];
__device__ float g_attn[B_*S_*H_];
__device__ float g_tmp[B_*S_*H_];
__device__ float g_ff[B_*S_*DFF_];
__device__ float g_h1[B_*S_*H_];
__device__ float g_logits[B_*S_*NC_];
__device__ uint32_t g_Whi[W_TOTAL];
__device__ uint32_t g_Wlo[W_TOTAL];

// ---------------- utils ----------
__device__ __forceinline__ float gelu_exact(float x) {
    return 0.5f * x * (1.0f + erff(x * 0.70710678118654752440f));
}

// split a float2 into packed bf16x2 hi and lo: x = hi + lo + O(2^-18 x)
__device__ __forceinline__ void bf16_split2(float fx, float fy,
                                            uint32_t& hi, uint32_t& lo) {
    __nv_bfloat162 h = __float22bfloat162_rn(make_float2(fx, fy));
    hi = *(uint32_t*)&h;
    float2 hf = __bfloat1622float2(h);
    __nv_bfloat162 l = __float22bfloat162_rn(make_float2(fx - hf.x, fy - hf.y));
    lo = *(uint32_t*)&l;
}

__device__ __forceinline__ void mma_bf16(float* d, const uint32_t* a,
                                         uint32_t b0, uint32_t b1) {
    asm volatile(
        "mma.sync.aligned.m16n8k16.row.col.f32.bf16.bf16.f32 "
        "{%0,%1,%2,%3},{%4,%5,%6,%7},{%8,%9},{%0,%1,%2,%3};"
        : "+f"(d[0]), "+f"(d[1]), "+f"(d[2]), "+f"(d[3])
        : "r"(a[0]), "r"(a[1]), "r"(a[2]), "r"(a[3]), "r"(b0), "r"(b1));
}

// ---------------- merged weight split + transpose + accumulator zero -------
// W[N][K] -> hi/lo [K/2][N] per layer, 5 regions dispatched by global id.
__global__ void split_all_kernel(const float* __restrict__ qkv_w,
                                 const float* __restrict__ out_w,
                                 const float* __restrict__ ff1_w,
                                 const float* __restrict__ ff2_w,
                                 const float* __restrict__ h1_w) {
    int id = blockIdx.x * blockDim.x + threadIdx.x;
    if (id < B_*S_*3) g_sumxyz[id]  = 0.f;
    if (id < B_*S_*4) g_sumfeat[id] = 0.f;
    if (id < B_*S_)   g_cnt[id]     = 0.f;
    if (id >= W_TOTAL) return;
    const float* src; int Nw, Kp, off, lsS, lsD, rel;
    if (id < 262144) {
        if (id < 196608) { src=qkv_w; Nw=768;  Kp=128; off=OFF_QKV; lsS=196608; lsD=98304;  rel=id; }
        else             { src=out_w; Nw=256;  Kp=128; off=OFF_OUT; lsS=65536;  lsD=32768;  rel=id-196608; }
    } else if (id < 524288) {
        src=ff1_w; Nw=1024; Kp=128; off=OFF_FF1; lsS=262144; lsD=131072; rel=id-262144;
    } else if (id < 786432) {
        src=ff2_w; Nw=256;  Kp=512; off=OFF_FF2; lsS=262144; lsD=131072; rel=id-524288;
    } else {
        src=h1_w;  Nw=256;  Kp=128; off=OFF_H1;  lsS=0;      lsD=0;      rel=id-786432;
    }
    int l   = rel / (Kp * Nw);
    int r2  = rel - l * (Kp * Nw);
    int n   = r2 / Kp;
    int kp  = r2 - n * Kp;
    const float* s = src + (size_t)l*lsS + (size_t)n*(2*Kp) + 2*kp;
    uint32_t h, lw;
    bf16_split2(s[0], s[1], h, lw);
    size_t d = (size_t)off + (size_t)l*lsD + (size_t)kp*Nw + n;
    g_Whi[d] = h;
    g_Wlo[d] = lw;
}

// ---------------- point -> seed argmin + block-local segment sums ----------
__global__ void assign_kernel(const float* __restrict__ xyz,
                              const float* __restrict__ feat,
                              const int*   __restrict__ seed_idx) {
    __shared__ float4 s_seed[S_];
    __shared__ float s_acc[S_*8];
    int b     = blockIdx.x >> 4;
    int chunk = blockIdx.x & 15;
    int tid   = threadIdx.x;

    {
        int idx = seed_idx[tid];
        float a0 = xyz[(size_t)(b*N_ + idx)*3 + 0];
        float a1 = xyz[(size_t)(b*N_ + idx)*3 + 1];
        float a2 = xyz[(size_t)(b*N_ + idx)*3 + 2];
        s_seed[tid] = make_float4(a0, a1, a2, (a0*a0 + a1*a1) + a2*a2);
    }
    #pragma unroll
    for (int i = 0; i < 8; i++) s_acc[tid + i*256] = 0.f;
    __syncthreads();

    for (int pp = 0; pp < 2; pp++) {
        int n0 = chunk*2048 + pp*1024;
        float px[4], py[4], pz[4], pw[4];
        #pragma unroll
        for (int i = 0; i < 4; i++) {
            size_t off = (size_t)(b*N_ + n0 + i*256 + tid);
            px[i] = xyz[off*3+0];
            py[i] = xyz[off*3+1];
            pz[i] = xyz[off*3+2];
            pw[i] = (px[i]*px[i] + py[i]*py[i]) + pz[i]*pz[i];
        }
        float best[4] = {INFINITY, INFINITY, INFINITY, INFINITY};
        int   bi[4]   = {0, 0, 0, 0};
        #pragma unroll 2
        for (int s = 0; s < S_; s++) {
            float4 sd = s_seed[s];
            #pragma unroll
            for (int i = 0; i < 4; i++) {
                float d = px[i] * sd.x;
                d = fmaf(py[i], sd.y, d);
                d = fmaf(pz[i], sd.z, d);
                float d2 = (pw[i] + sd.w) - 2.0f*d;
                if (d2 < best[i]) { best[i] = d2; bi[i] = s; }  // first wins
            }
        }
        #pragma unroll
        for (int i = 0; i < 4; i++) {
            size_t off = (size_t)(b*N_ + n0 + i*256 + tid);
            g_assign[off] = bi[i];
            float4 f = ((const float4*)feat)[off];
            float* a = &s_acc[bi[i]*8];
            atomicAdd(a+0, px[i]); atomicAdd(a+1, py[i]); atomicAdd(a+2, pz[i]);
            atomicAdd(a+3, f.x);   atomicAdd(a+4, f.y);
            atomicAdd(a+5, f.z);   atomicAdd(a+6, f.w);
            atomicAdd(a+7, 1.0f);
        }
    }
    __syncthreads();

    int s  = tid;
    int bs = b*S_ + s;
    atomicAdd(&g_sumxyz [bs*3+0], s_acc[s*8+0]);
    atomicAdd(&g_sumxyz [bs*3+1], s_acc[s*8+1]);
    atomicAdd(&g_sumxyz [bs*3+2], s_acc[s*8+2]);
    atomicAdd(&g_sumfeat[bs*4+0], s_acc[s*8+3]);
    atomicAdd(&g_sumfeat[bs*4+1], s_acc[s*8+4]);
    atomicAdd(&g_sumfeat[bs*4+2], s_acc[s*8+5]);
    atomicAdd(&g_sumfeat[bs*4+3], s_acc[s*8+6]);
    atomicAdd(&g_cnt[bs],         s_acc[s*8+7]);
}

// ---------------- superpoint features -> token projection ----------
// 512 blocks x 8 rows: sp vectors computed in parallel (thread (r,c) -> one
// element), one barrier, then each thread emits its channel for all 8 rows.
__global__ void tokens_kernel(const float* __restrict__ xyz,
                              const int*   __restrict__ seed_idx,
                              const float* __restrict__ pw,
                              const float* __restrict__ pb) {
    __shared__ float sp[8][8];
    int tid = threadIdx.x;
    int blk = blockIdx.x;            // 0..511
    if (tid < 64) {
        int r = tid >> 3, c = tid & 7;
        if (c < 7) {
            int bs = blk*8 + r;
            int b = bs >> 8, s = bs & 255;
            float cnt   = g_cnt[bs];
            float denom = fmaxf(cnt, 1.0f);
            bool  empty = (cnt == 0.0f);
            float v;
            if (c < 3) {
                int idx = seed_idx[s];
                float seedc = xyz[(size_t)(b*N_ + idx)*3 + c];
                v = empty ? seedc : g_sumxyz[bs*3 + c] / denom;
            } else {
                v = empty ? 0.f : g_sumfeat[bs*4 + (c - 3)] / denom;
            }
            sp[r][c] = v;
        }
    }
    float w[7];
    #pragma unroll
    for (int i = 0; i < 7; i++) w[i] = pw[tid*7 + i];
    float bb = pb[tid];
    __syncthreads();
    #pragma unroll
    for (int r = 0; r < 8; r++) {
        float acc = 0.f;
        #pragma unroll
        for (int i = 0; i < 7; i++) acc = fmaf(sp[r][i], w[i], acc);
        g_x[(size_t)(blk*8 + r)*H_ + tid] = acc + bb;
    }
}

// ---------------- tensor-core GEMM (3xBF16, m16n8k16): C = epi(A@Wt + b) ---
// A: fp32, split in-kernel. W: PRE-SPLIT transposed bf16 hi/lo [K/2][Nw].
// 3 passes: al*bh + ah*bl + ah*bh (dropped lo*lo ~2^-18).
// KT=16, double-buffered, +8 pad => conflict-free fragment LDS.
// EPI: 0 = none, 1 = gelu, 2 = +residual
template<int TM, int TN, int WM, int WN, int THREADS, int MINCTA, int EPI>
__global__ void __launch_bounds__(THREADS, MINCTA)
sgemm_tc(const float* __restrict__ A,
         const uint32_t* __restrict__ Whi, const uint32_t* __restrict__ Wlo,
         const float* __restrict__ bias, const float* __restrict__ res,
         float* __restrict__ C, int M, int N, int K, int Nw) {
    constexpr int KT = 16;
    constexpr int PA = TM + 8;
    constexpr int PB = TN + 8;
    constexpr int WCOLS = TN / WN;
    constexpr int MT = WM / 16;
    constexpr int NT = WN / 8;
    constexpr int NLA = TM * 4 / THREADS;   // A float4 loads per thread
    constexpr int WU  = TN * 2 / THREADS;   // W uint4 loads per thread per array
    constexpr int C4  = TN / 4;             // uint4 per kpair row

    __shared__ __align__(16) uint32_t As_hi[2][8][PA];
    __shared__ __align__(16) uint32_t As_lo[2][8][PA];
    __shared__ __align__(16) uint32_t Ws_hi[2][8][PB];
    __shared__ __align__(16) uint32_t Ws_lo[2][8][PB];

    const int tid  = threadIdx.x;
    const int lane = tid & 31;
    const int wid  = tid >> 5;
    const int wrow = wid / WCOLS;
    const int wcol = wid % WCOLS;
    const int gr   = lane >> 2;          // 0..7
    const int ct   = lane & 3;           // 0..3
    const int bm   = blockIdx.y * TM;
    const int bn   = blockIdx.x * TN;

    float acc[MT][NT][4];
    #pragma unroll
    for (int mt = 0; mt < MT; mt++)
        #pragma unroll
        for (int nt = 0; nt < NT; nt++)
            #pragma unroll
            for (int j = 0; j < 4; j++) acc[mt][nt][j] = 0.f;

    float4 av[NLA];
    uint4  wh[WU], wl[WU];

    #pragma unroll
    for (int t = 0; t < NLA; t++) {
        int id = tid + t*THREADS, r = id >> 2, kq = id & 3;
        av[t] = *(const float4*)(A + (size_t)(bm + r)*K + kq*4);
    }
    #pragma unroll
    for (int t = 0; t < WU; t++) {
        int u = tid + t*THREADS, kp = u / C4, c4 = u % C4;
        size_t base = (size_t)kp*Nw + bn + c4*4;
        wh[t] = *(const uint4*)(Whi + base);
        wl[t] = *(const uint4*)(Wlo + base);
    }

    auto stage = [&](int buf) {
        #pragma unroll
        for (int t = 0; t < NLA; t++) {
            int id = tid + t*THREADS, r = id >> 2, kq = id & 3;
            uint32_t h0, l0, h1, l1;
            bf16_split2(av[t].x, av[t].y, h0, l0);
            bf16_split2(av[t].z, av[t].w, h1, l1);
            As_hi[buf][2*kq  ][r] = h0;
            As_hi[buf][2*kq+1][r] = h1;
            As_lo[buf][2*kq  ][r] = l0;
            As_lo[buf][2*kq+1][r] = l1;
        }
        #pragma unroll
        for (int t = 0; t < WU; t++) {
            int u = tid + t*THREADS, kp = u / C4, c4 = u % C4;
            *(uint4*)&Ws_hi[buf][kp][c4*4] = wh[t];
            *(uint4*)&Ws_lo[buf][kp][c4*4] = wl[t];
        }
    };

    stage(0);
    __syncthreads();

    const int nk = K / KT;
    for (int kt = 0; kt < nk; kt++) {
        const int buf = kt & 1;
        if (kt + 1 < nk) {
            int k0 = (kt + 1) * KT;
            #pragma unroll
            for (int t = 0; t < NLA; t++) {
                int id = tid + t*THREADS, r = id >> 2, kq = id & 3;
                av[t] = *(const float4*)(A + (size_t)(bm + r)*K + k0 + kq*4);
            }
            int kp0 = (kt + 1) * 8;
            #pragma unroll
            for (int t = 0; t < WU; t++) {
                int u = tid + t*THREADS, kp = u / C4, c4 = u % C4;
                size_t base = (size_t)(kp0 + kp)*Nw + bn + c4*4;
                wh[t] = *(const uint4*)(Whi + base);
                wl[t] = *(const uint4*)(Wlo + base);
            }
        }

        uint32_t ah[MT][4], al[MT][4];
        #pragma unroll
        for (int mt = 0; mt < MT; mt++) {
            int m = wrow*WM + mt*16 + gr;
            ah[mt][0] = As_hi[buf][ct  ][m];
            ah[mt][1] = As_hi[buf][ct  ][m + 8];
            ah[mt][2] = As_hi[buf][ct+4][m];
            ah[mt][3] = As_hi[buf][ct+4][m + 8];
            al[mt][0] = As_lo[buf][ct  ][m];
            al[mt][1] = As_lo[buf][ct  ][m + 8];
            al[mt][2] = As_lo[buf][ct+4][m];
            al[mt][3] = As_lo[buf][ct+4][m + 8];
        }
        #pragma unroll
        for (int nt = 0; nt < NT; nt++) {
            int n = wcol*WN + nt*8 + gr;
            uint32_t bh0 = Ws_hi[buf][ct  ][n];
            uint32_t bh1 = Ws_hi[buf][ct+4][n];
            uint32_t bl0 = Ws_lo[buf][ct  ][n];
            uint32_t bl1 = Ws_lo[buf][ct+4][n];
            #pragma unroll
            for (int mt = 0; mt < MT; mt++) {
                mma_bf16(acc[mt][nt], al[mt], bh0, bh1);   // lo*hi
                mma_bf16(acc[mt][nt], ah[mt], bl0, bl1);   // hi*lo
                mma_bf16(acc[mt][nt], ah[mt], bh0, bh1);   // hi*hi
            }
        }

        if (kt + 1 < nk) stage(buf ^ 1);
        __syncthreads();
    }

    // epilogue: C-frag m16n8: c0,c1 at (gr, ct*2..+1), c2,c3 at (gr+8, same)
    #pragma unroll
    for (int mt = 0; mt < MT; mt++) {
        int row = bm + wrow*WM + mt*16 + gr;
        #pragma unroll
        for (int nt = 0; nt < NT; nt++) {
            int col = bn + wcol*WN + nt*8 + ct*2;
            float b0 = bias[col], b1 = bias[col + 1];
            float c0 = acc[mt][nt][0] + b0;
            float c1 = acc[mt][nt][1] + b1;
            float c2 = acc[mt][nt][2] + b0;
            float c3 = acc[mt][nt][3] + b1;
            if (EPI == 1) {
                c0 = gelu_exact(c0); c1 = gelu_exact(c1);
                c2 = gelu_exact(c2); c3 = gelu_exact(c3);
            }
            if (EPI == 2) {
                float2 r0 = *(const float2*)(res + (size_t)row*N + col);
                float2 r1 = *(const float2*)(res + (size_t)(row + 8)*N + col);
                c0 += r0.x; c1 += r0.y; c2 += r1.x; c3 += r1.y;
            }
            *(float2*)(C + (size_t)row*N + col)       = make_float2(c0, c1);
            *(float2*)(C + (size_t)(row + 8)*N + col) = make_float2(c2, c3);
        }
    }
}

// ---------------- attention: split-K with in-warp merge ---------------------
// grid = B*NH*2 (query halves), 256 threads. Thread pair (2q, 2q+1) handles
// the SAME query over key halves [0,128) / [128,256); partial online-softmax
// states merge via shfl_xor(1) (partner always in-warp).
__global__ void attention_kernel(const float* __restrict__ qkv,
                                 float* __restrict__ outp) {
    __shared__ float Ks[S_][DH_];
    int bid  = blockIdx.x;
    int half = bid & 1;
    int bh   = bid >> 1;
    int b    = bh >> 3, h = bh & 7;
    int tid  = threadIdx.x;                 // 0..255
    const float* base = qkv + (size_t)b*S_*(3*H_);
    {
        const float4* kr = (const float4*)(base + (size_t)tid*(3*H_) + H_ + h*DH_);
        float4* dst = (float4*)&Ks[tid][0];
        #pragma unroll
        for (int i = 0; i < DH_/4; i++) dst[i] = kr[i];
    }
    int qlocal = tid >> 1;                  // 0..127
    int ks     = tid & 1;                   // key half
    int qrow   = half*128 + qlocal;
    float q[DH_];
    {
        const float4* qr = (const float4*)(base + (size_t)qrow*(3*H_) + h*DH_);
        #pragma unroll
        for (int i = 0; i < DH_/4; i++) ((float4*)q)[i] = qr[i];
    }
    __syncthreads();

    const float scale = 0.17677669529663688110f;   // 1/sqrt(32)
    float m = -INFINITY, l = 0.f;
    float acc[DH_];
    #pragma unroll
    for (int d = 0; d < DH_; d++) acc[d] = 0.f;
    const float* vbase = base + 2*H_ + h*DH_;
    const int j0 = ks * 128;

    for (int jj = 0; jj < 128; jj += 2) {
        int j = j0 + jj;
        float d0 = 0.f, d1 = 0.f, d2 = 0.f, d3 = 0.f;
        float e0 = 0.f, e1 = 0.f, e2 = 0.f, e3 = 0.f;
        #pragma unroll
        for (int i = 0; i < DH_/4; i++) {
            float4 k0 = ((const float4*)&Ks[j][0])[i];
            float4 k1 = ((const float4*)&Ks[j+1][0])[i];
            d0 = fmaf(q[4*i+0], k0.x, d0);
            d1 = fmaf(q[4*i+1], k0.y, d1);
            d2 = fmaf(q[4*i+2], k0.z, d2);
            d3 = fmaf(q[4*i+3], k0.w, d3);
            e0 = fmaf(q[4*i+0], k1.x, e0);
            e1 = fmaf(q[4*i+1], k1.y, e1);
            e2 = fmaf(q[4*i+2], k1.z, e2);
            e3 = fmaf(q[4*i+3], k1.w, e3);
        }
        float s0 = ((d0 + d1) + (d2 + d3)) * scale;
        float s1 = ((e0 + e1) + (e2 + e3)) * scale;
        float mn = fmaxf(m, fmaxf(s0, s1));
        float c  = __expf(m - mn);
        float p0 = __expf(s0 - mn);
        float p1 = __expf(s1 - mn);
        l = l*c + p0 + p1;
        const float4* v0 = (const float4*)(vbase + (size_t)j*(3*H_));
        const float4* v1 = (const float4*)(vbase + (size_t)(j+1)*(3*H_));
        #pragma unroll
        for (int i = 0; i < DH_/4; i++) {
            float4 a = v0[i], bq = v1[i];
            acc[i*4+0] = fmaf(acc[i*4+0], c, fmaf(p0, a.x, p1*bq.x));
            acc[i*4+1] = fmaf(acc[i*4+1], c, fmaf(p0, a.y, p1*bq.y));
            acc[i*4+2] = fmaf(acc[i*4+2], c, fmaf(p0, a.z, p1*bq.z));
            acc[i*4+3] = fmaf(acc[i*4+3], c, fmaf(p0, a.w, p1*bq.w));
        }
        m = mn;
    }

    // merge partial softmax state with partner lane (other key half)
    float mo = __shfl_xor_sync(0xffffffffu, m, 1);
    float lo = __shfl_xor_sync(0xffffffffu, l, 1);
    float mn = fmaxf(m, mo);
    float c1 = __expf(m  - mn);
    float c2 = __expf(mo - mn);
    float ltot = l*c1 + lo*c2;
    float inv = 1.0f / ltot;
    #pragma unroll
    for (int d = 0; d < DH_; d++) {
        float ao = __shfl_xor_sync(0xffffffffu, acc[d], 1);
        acc[d] = (acc[d]*c1 + ao*c2) * inv;
    }
    // both lanes hold the full result; each writes half (4 float4 each)
    float* orow = outp + (size_t)(b*S_ + qrow)*H_ + h*DH_ + ks*16;
    #pragma unroll
    for (int i = 0; i < 4; i++)
        ((float4*)orow)[i] = ((float4*)&acc[ks*16])[i];
}

// ---------------- layernorm: warp-per-row, barrier-free ----------
__global__ void layernorm_kernel(const float* __restrict__ in,
                                 const float* __restrict__ gw,
                                 const float* __restrict__ gb,
                                 float* __restrict__ outp) {
    int warp = threadIdx.x >> 5;
    int lane = threadIdx.x & 31;
    int row  = blockIdx.x * 8 + warp;
    const float4* in4 = (const float4*)in;
    float4 a = in4[(size_t)row*64 + lane*2];
    float4 b = in4[(size_t)row*64 + lane*2 + 1];
    float s1 = ((a.x + a.y) + (a.z + a.w)) + ((b.x + b.y) + (b.z + b.w));
    float s2 = ((a.x*a.x + a.y*a.y) + (a.z*a.z + a.w*a.w))
             + ((b.x*b.x + b.y*b.y) + (b.z*b.z + b.w*b.w));
    #pragma unroll
    for (int o = 16; o > 0; o >>= 1) {
        s1 += __shfl_xor_sync(0xffffffffu, s1, o);
        s2 += __shfl_xor_sync(0xffffffffu, s2, o);
    }
    float mean = s1 * (1.0f/H_);
    float var  = s2 * (1.0f/H_) - mean*mean;
    float rstd = rsqrtf(var + 1e-5f);
    float4 g0 = ((const float4*)gw)[lane*2];
    float4 g1 = ((const float4*)gw)[lane*2 + 1];
    float4 o0 = ((const float4*)gb)[lane*2];
    float4 o1 = ((const float4*)gb)[lane*2 + 1];
    float4 r0, r1;
    r0.x = (a.x - mean)*rstd*g0.x + o0.x;
    r0.y = (a.y - mean)*rstd*g0.y + o0.y;
    r0.z = (a.z - mean)*rstd*g0.z + o0.z;
    r0.w = (a.w - mean)*rstd*g0.w + o0.w;
    r1.x = (b.x - mean)*rstd*g1.x + o1.x;
    r1.y = (b.y - mean)*rstd*g1.y + o1.y;
    r1.z = (b.z - mean)*rstd*g1.z + o1.z;
    r1.w = (b.w - mean)*rstd*g1.w + o1.w;
    ((float4*)outp)[(size_t)row*64 + lane*2]     = r0;
    ((float4*)outp)[(size_t)row*64 + lane*2 + 1] = r1;
}

// ---------------- head2: logits (M x 13), one thread per output ----------
__global__ void head2_kernel(const float* __restrict__ X,
                             const float* __restrict__ W,
                             const float* __restrict__ bias) {
    int t = blockIdx.x * blockDim.x + threadIdx.x;
    if (t >= B_*S_*NC_) return;
    int row = t / NC_, c = t - row*NC_;
    const float4* x = (const float4*)(X + (size_t)row*H_);
    const float4* w = (const float4*)(W + (size_t)c*H_);
    float s0 = 0.f, s1 = 0.f, s2 = 0.f, s3 = 0.f;
    #pragma unroll 8
    for (int k = 0; k < H_/4; k++) {
        float4 xv = x[k], wv = w[k];
        s0 = fmaf(xv.x, wv.x, s0); s1 = fmaf(xv.y, wv.y, s1);
        s2 = fmaf(xv.z, wv.z, s2); s3 = fmaf(xv.w, wv.w, s3);
    }
    g_logits[t] = (s0+s1) + (s2+s3) + bias[c];
}

// ---------------- final gather to point logits ----------
__global__ void gather_kernel(float* __restrict__ out) {
    int t = blockIdx.x * blockDim.x + threadIdx.x;
    if (t >= B_*N_*NC_) return;
    int r = t / NC_;
    int c = t - r*NC_;
    int b = r >> 15;                // r / N_
    int a = g_assign[r];
    out[t] = g_logits[(b*S_ + a)*NC_ + c];
}

// ---------------- host launcher ----------
extern "C" void kernel_launch(void* const* d_in, const int* in_sizes, int n_in,
                              void* d_out, int out_size) {
    const float* xyz      = (const float*)d_in[0];
    const float* feat     = (const float*)d_in[1];
    const int*   seed_idx = (const int*)  d_in[2];
    const float* proj_w   = (const float*)d_in[3];
    const float* proj_b   = (const float*)d_in[4];
    const float* qkv_w    = (const float*)d_in[5];
    const float* qkv_b    = (const float*)d_in[6];
    const float* out_w    = (const float*)d_in[7];
    const float* out_b    = (const float*)d_in[8];
    const float* ln1_g    = (const float*)d_in[9];
    const float* ln1_b    = (const float*)d_in[10];
    const float* ln2_g    = (const float*)d_in[11];
    const float* ln2_b    = (const float*)d_in[12];
    const float* ff1_w    = (const float*)d_in[13];
    const float* ff1_b    = (const float*)d_in[14];
    const float* ff2_w    = (const float*)d_in[15];
    const float* ff2_b    = (const float*)d_in[16];
    const float* hln_g    = (const float*)d_in[17];
    const float* hln_b    = (const float*)d_in[18];
    const float* h1_w     = (const float*)d_in[19];
    const float* h1_b     = (const float*)d_in[20];
    const float* h2_w     = (const float*)d_in[21];
    const float* h2_b     = (const float*)d_in[22];
    float* out = (float*)d_out;

    float *p_x, *p_qkv, *p_attn, *p_tmp, *p_ff, *p_h1;
    uint32_t *p_Whi, *p_Wlo;
    cudaGetSymbolAddress((void**)&p_x,    g_x);
    cudaGetSymbolAddress((void**)&p_qkv,  g_qkv);
    cudaGetSymbolAddress((void**)&p_attn, g_attn);
    cudaGetSymbolAddress((void**)&p_tmp,  g_tmp);
    cudaGetSymbolAddress((void**)&p_ff,   g_ff);
    cudaGetSymbolAddress((void**)&p_h1,   g_h1);
    cudaGetSymbolAddress((void**)&p_Whi,  g_Whi);
    cudaGetSymbolAddress((void**)&p_Wlo,  g_Wlo);

    const int M = B_*S_;   // 4096

    split_all_kernel<<<(W_TOTAL + 255)/256, 256>>>(qkv_w, out_w, ff1_w,
                                                   ff2_w, h1_w);
    assign_kernel<<<B_*16, 256>>>(xyz, feat, seed_idx);
    tokens_kernel<<<M/8, 256>>>(xyz, seed_idx, proj_w, proj_b);

    for (int l = 0; l < 2; l++) {
        // QKV: M=4096, N=768, K=256 -> 64x128 tiles, grid 6x64=384
        sgemm_tc<64,128,64,32,128,4,0><<<dim3(3*H_/128, M/64), 128>>>(
            p_x, p_Whi+OFF_QKV + l*98304, p_Wlo+OFF_QKV + l*98304,
            qkv_b + l*3*H_, nullptr, p_qkv, M, 3*H_, H_, 768);
        attention_kernel<<<B_*NH_*2, 256>>>(p_qkv, p_attn);
        // out-proj: N=256, K=256 -> 64x64 tiles, grid 4x64=256, +residual
        sgemm_tc<64,64,32,32,128,4,2><<<dim3(H_/64, M/64), 128>>>(
            p_attn, p_Whi+OFF_OUT + l*32768, p_Wlo+OFF_OUT + l*32768,
            out_b + l*H_, p_x, p_tmp, M, H_, H_, 256);
        layernorm_kernel<<<M/8, 256>>>(p_tmp, ln1_g + l*H_, ln1_b + l*H_, p_x);
        // FF1: N=1024, K=256 -> 64x128 tiles, grid 8x64=512, gelu
        sgemm_tc<64,128,64,32,128,4,1><<<dim3(DFF_/128, M/64), 128>>>(
            p_x, p_Whi+OFF_FF1 + l*131072, p_Wlo+OFF_FF1 + l*131072,
            ff1_b + l*DFF_, nullptr, p_ff, M, DFF_, H_, 1024);
        // FF2: N=256, K=1024 -> 64x64 tiles, +residual
        sgemm_tc<64,64,32,32,128,4,2><<<dim3(H_/64, M/64), 128>>>(
            p_ff, p_Whi+OFF_FF2 + l*131072, p_Wlo+OFF_FF2 + l*131072,
            ff2_b + l*H_, p_x, p_tmp, M, H_, DFF_, 256);
        layernorm_kernel<<<M/8, 256>>>(p_tmp, ln2_g + l*H_, ln2_b + l*H_, p_x);
    }

    layernorm_kernel<<<M/8, 256>>>(p_x, hln_g, hln_b, p_tmp);
    sgemm_tc<64,64,32,32,128,4,1><<<dim3(H_/64, M/64), 128>>>(
        p_tmp, p_Whi+OFF_H1, p_Wlo+OFF_H1, h1_b, nullptr, p_h1,
        M, H_, H_, 256);
    head2_kernel<<<(M*NC_ + 255)/256, 256>>>(p_h1, h2_w, h2_b);
    gather_kernel<<<(B_*N_*NC_ + 255)/256, 256>>>(out);
}

// round 17
// speedup vs baseline: 1.5910x; 1.0447x over previous
#include <cuda_runtime.h>
#include <cuda_bf16.h>
#include <math.h>
#include <stdint.h>

#define B_   16
#define N_   32768
#define S_   256
#define H_   256
#define NH_  8
#define DH_  32
#define DFF_ 1024
#define NC_  13

// pre-split transposed weight pool offsets (uint32 elements)
#define OFF_QKV 0
#define OFF_OUT 196608
#define OFF_FF1 262144
#define OFF_FF2 524288
#define OFF_H1  786432
#define W_TOTAL 819200

// ---------------- scratch (device globals; no allocations allowed) ----------
__device__ float g_sumxyz[B_*S_*3];
__device__ float g_sumfeat[B_*S_*4];
__device__ float g_cnt[B_*S_];
__device__ int   g_assign[B_*N_];
__device__ float g_x[B_*S_*H_];
__device__ float g_qkv[B_*S_*3*H_];
__device__ float g_attn[B_*S_*H_];
__device__ float g_tmp[B_*S_*H_];
__device__ float g_ff[B_*S_*DFF_];
__device__ float g_h1[B_*S_*H_];
__device__ float g_logits[B_*S_*NC_];
__device__ uint32_t g_Whi[W_TOTAL];
__device__ uint32_t g_Wlo[W_TOTAL];

// ---------------- utils ----------
__device__ __forceinline__ float gelu_exact(float x) {
    return 0.5f * x * (1.0f + erff(x * 0.70710678118654752440f));
}

// split a float2 into packed bf16x2 hi and lo: x = hi + lo + O(2^-18 x)
__device__ __forceinline__ void bf16_split2(float fx, float fy,
                                            uint32_t& hi, uint32_t& lo) {
    __nv_bfloat162 h = __float22bfloat162_rn(make_float2(fx, fy));
    hi = *(uint32_t*)&h;
    float2 hf = __bfloat1622float2(h);
    __nv_bfloat162 l = __float22bfloat162_rn(make_float2(fx - hf.x, fy - hf.y));
    lo = *(uint32_t*)&l;
}

__device__ __forceinline__ void mma_bf16(float* d, const uint32_t* a,
                                         uint32_t b0, uint32_t b1) {
    asm volatile(
        "mma.sync.aligned.m16n8k16.row.col.f32.bf16.bf16.f32 "
        "{%0,%1,%2,%3},{%4,%5,%6,%7},{%8,%9},{%0,%1,%2,%3};"
        : "+f"(d[0]), "+f"(d[1]), "+f"(d[2]), "+f"(d[3])
        : "r"(a[0]), "r"(a[1]), "r"(a[2]), "r"(a[3]), "r"(b0), "r"(b1));
}

// ---------------- merged weight split + transpose + accumulator zero -------
// W[N][K] -> hi/lo [K/2][N] per layer, 5 regions dispatched by global id.
__global__ void split_all_kernel(const float* __restrict__ qkv_w,
                                 const float* __restrict__ out_w,
                                 const float* __restrict__ ff1_w,
                                 const float* __restrict__ ff2_w,
                                 const float* __restrict__ h1_w) {
    int id = blockIdx.x * blockDim.x + threadIdx.x;
    if (id < B_*S_*3) g_sumxyz[id]  = 0.f;
    if (id < B_*S_*4) g_sumfeat[id] = 0.f;
    if (id < B_*S_)   g_cnt[id]     = 0.f;
    if (id >= W_TOTAL) return;
    const float* src; int Nw, Kp, off, lsS, lsD, rel;
    if (id < 262144) {
        if (id < 196608) { src=qkv_w; Nw=768;  Kp=128; off=OFF_QKV; lsS=196608; lsD=98304;  rel=id; }
        else             { src=out_w; Nw=256;  Kp=128; off=OFF_OUT; lsS=65536;  lsD=32768;  rel=id-196608; }
    } else if (id < 524288) {
        src=ff1_w; Nw=1024; Kp=128; off=OFF_FF1; lsS=262144; lsD=131072; rel=id-262144;
    } else if (id < 786432) {
        src=ff2_w; Nw=256;  Kp=512; off=OFF_FF2; lsS=262144; lsD=131072; rel=id-524288;
    } else {
        src=h1_w;  Nw=256;  Kp=128; off=OFF_H1;  lsS=0;      lsD=0;      rel=id-786432;
    }
    int l   = rel / (Kp * Nw);
    int r2  = rel - l * (Kp * Nw);
    int n   = r2 / Kp;
    int kp  = r2 - n * Kp;
    const float* s = src + (size_t)l*lsS + (size_t)n*(2*Kp) + 2*kp;
    uint32_t h, lw;
    bf16_split2(s[0], s[1], h, lw);
    size_t d = (size_t)off + (size_t)l*lsD + (size_t)kp*Nw + n;
    g_Whi[d] = h;
    g_Wlo[d] = lw;
}

// ---------------- point -> seed argmin + block-local segment sums ----------
// Seeds staged as (-2x, -2y, -2z, |s|^2); argmin runs on s2 - 2*dot (the
// per-point |p|^2 constant cancels in the comparison) -> 3-FMA inner chain.
__global__ void assign_kernel(const float* __restrict__ xyz,
                              const float* __restrict__ feat,
                              const int*   __restrict__ seed_idx) {
    __shared__ float4 s_seed[S_];
    __shared__ float s_acc[S_*8];
    int b     = blockIdx.x >> 4;
    int chunk = blockIdx.x & 15;
    int tid   = threadIdx.x;

    {
        int idx = seed_idx[tid];
        float a0 = xyz[(size_t)(b*N_ + idx)*3 + 0];
        float a1 = xyz[(size_t)(b*N_ + idx)*3 + 1];
        float a2 = xyz[(size_t)(b*N_ + idx)*3 + 2];
        s_seed[tid] = make_float4(-2.0f*a0, -2.0f*a1, -2.0f*a2,
                                  (a0*a0 + a1*a1) + a2*a2);
    }
    #pragma unroll
    for (int i = 0; i < 8; i++) s_acc[tid + i*256] = 0.f;
    __syncthreads();

    for (int pp = 0; pp < 2; pp++) {
        int n0 = chunk*2048 + pp*1024;
        float px[4], py[4], pz[4];
        #pragma unroll
        for (int i = 0; i < 4; i++) {
            size_t off = (size_t)(b*N_ + n0 + i*256 + tid);
            px[i] = xyz[off*3+0];
            py[i] = xyz[off*3+1];
            pz[i] = xyz[off*3+2];
        }
        float best[4] = {INFINITY, INFINITY, INFINITY, INFINITY};
        int   bi[4]   = {0, 0, 0, 0};
        #pragma unroll 2
        for (int s = 0; s < S_; s++) {
            float4 sd = s_seed[s];
            #pragma unroll
            for (int i = 0; i < 4; i++) {
                float d2 = fmaf(px[i], sd.x,
                           fmaf(py[i], sd.y,
                           fmaf(pz[i], sd.z, sd.w)));
                if (d2 < best[i]) { best[i] = d2; bi[i] = s; }  // first wins
            }
        }
        #pragma unroll
        for (int i = 0; i < 4; i++) {
            size_t off = (size_t)(b*N_ + n0 + i*256 + tid);
            g_assign[off] = bi[i];
            float4 f = ((const float4*)feat)[off];
            float* a = &s_acc[bi[i]*8];
            atomicAdd(a+0, px[i]); atomicAdd(a+1, py[i]); atomicAdd(a+2, pz[i]);
            atomicAdd(a+3, f.x);   atomicAdd(a+4, f.y);
            atomicAdd(a+5, f.z);   atomicAdd(a+6, f.w);
            atomicAdd(a+7, 1.0f);
        }
    }
    __syncthreads();

    int s  = tid;
    int bs = b*S_ + s;
    atomicAdd(&g_sumxyz [bs*3+0], s_acc[s*8+0]);
    atomicAdd(&g_sumxyz [bs*3+1], s_acc[s*8+1]);
    atomicAdd(&g_sumxyz [bs*3+2], s_acc[s*8+2]);
    atomicAdd(&g_sumfeat[bs*4+0], s_acc[s*8+3]);
    atomicAdd(&g_sumfeat[bs*4+1], s_acc[s*8+4]);
    atomicAdd(&g_sumfeat[bs*4+2], s_acc[s*8+5]);
    atomicAdd(&g_sumfeat[bs*4+3], s_acc[s*8+6]);
    atomicAdd(&g_cnt[bs],         s_acc[s*8+7]);
}

// ---------------- superpoint features -> token projection ----------
__global__ void tokens_kernel(const float* __restrict__ xyz,
                              const int*   __restrict__ seed_idx,
                              const float* __restrict__ pw,
                              const float* __restrict__ pb) {
    __shared__ float sp[8][8];
    int tid = threadIdx.x;
    int blk = blockIdx.x;            // 0..511
    if (tid < 64) {
        int r = tid >> 3, c = tid & 7;
        if (c < 7) {
            int bs = blk*8 + r;
            int b = bs >> 8, s = bs & 255;
            float cnt   = g_cnt[bs];
            float denom = fmaxf(cnt, 1.0f);
            bool  empty = (cnt == 0.0f);
            float v;
            if (c < 3) {
                int idx = seed_idx[s];
                float seedc = xyz[(size_t)(b*N_ + idx)*3 + c];
                v = empty ? seedc : g_sumxyz[bs*3 + c] / denom;
            } else {
                v = empty ? 0.f : g_sumfeat[bs*4 + (c - 3)] / denom;
            }
            sp[r][c] = v;
        }
    }
    float w[7];
    #pragma unroll
    for (int i = 0; i < 7; i++) w[i] = pw[tid*7 + i];
    float bb = pb[tid];
    __syncthreads();
    #pragma unroll
    for (int r = 0; r < 8; r++) {
        float acc = 0.f;
        #pragma unroll
        for (int i = 0; i < 7; i++) acc = fmaf(sp[r][i], w[i], acc);
        g_x[(size_t)(blk*8 + r)*H_ + tid] = acc + bb;
    }
}

// ---------------- tensor-core GEMM (3xBF16, m16n8k16): C = epi(A@Wt + b) ---
// A: fp32, split in-kernel. W: PRE-SPLIT transposed bf16 hi/lo [K/2][Nw].
// 3 passes: al*bh + ah*bl + ah*bh (dropped lo*lo ~2^-18).
// KT=16, double-buffered, +8 pad => conflict-free fragment LDS.
// EPI: 0 = none, 1 = gelu, 2 = +residual
template<int TM, int TN, int WM, int WN, int THREADS, int MINCTA, int EPI>
__global__ void __launch_bounds__(THREADS, MINCTA)
sgemm_tc(const float* __restrict__ A,
         const uint32_t* __restrict__ Whi, const uint32_t* __restrict__ Wlo,
         const float* __restrict__ bias, const float* __restrict__ res,
         float* __restrict__ C, int M, int N, int K, int Nw) {
    constexpr int KT = 16;
    constexpr int PA = TM + 8;
    constexpr int PB = TN + 8;
    constexpr int WCOLS = TN / WN;
    constexpr int MT = WM / 16;
    constexpr int NT = WN / 8;
    constexpr int NLA = TM * 4 / THREADS;   // A float4 loads per thread
    constexpr int WU  = TN * 2 / THREADS;   // W uint4 loads per thread per array
    constexpr int C4  = TN / 4;             // uint4 per kpair row

    __shared__ __align__(16) uint32_t As_hi[2][8][PA];
    __shared__ __align__(16) uint32_t As_lo[2][8][PA];
    __shared__ __align__(16) uint32_t Ws_hi[2][8][PB];
    __shared__ __align__(16) uint32_t Ws_lo[2][8][PB];

    const int tid  = threadIdx.x;
    const int lane = tid & 31;
    const int wid  = tid >> 5;
    const int wrow = wid / WCOLS;
    const int wcol = wid % WCOLS;
    const int gr   = lane >> 2;          // 0..7
    const int ct   = lane & 3;           // 0..3
    const int bm   = blockIdx.y * TM;
    const int bn   = blockIdx.x * TN;

    float acc[MT][NT][4];
    #pragma unroll
    for (int mt = 0; mt < MT; mt++)
        #pragma unroll
        for (int nt = 0; nt < NT; nt++)
            #pragma unroll
            for (int j = 0; j < 4; j++) acc[mt][nt][j] = 0.f;

    float4 av[NLA];
    uint4  wh[WU], wl[WU];

    #pragma unroll
    for (int t = 0; t < NLA; t++) {
        int id = tid + t*THREADS, r = id >> 2, kq = id & 3;
        av[t] = *(const float4*)(A + (size_t)(bm + r)*K + kq*4);
    }
    #pragma unroll
    for (int t = 0; t < WU; t++) {
        int u = tid + t*THREADS, kp = u / C4, c4 = u % C4;
        size_t base = (size_t)kp*Nw + bn + c4*4;
        wh[t] = *(const uint4*)(Whi + base);
        wl[t] = *(const uint4*)(Wlo + base);
    }

    auto stage = [&](int buf) {
        #pragma unroll
        for (int t = 0; t < NLA; t++) {
            int id = tid + t*THREADS, r = id >> 2, kq = id & 3;
            uint32_t h0, l0, h1, l1;
            bf16_split2(av[t].x, av[t].y, h0, l0);
            bf16_split2(av[t].z, av[t].w, h1, l1);
            As_hi[buf][2*kq  ][r] = h0;
            As_hi[buf][2*kq+1][r] = h1;
            As_lo[buf][2*kq  ][r] = l0;
            As_lo[buf][2*kq+1][r] = l1;
        }
        #pragma unroll
        for (int t = 0; t < WU; t++) {
            int u = tid + t*THREADS, kp = u / C4, c4 = u % C4;
            *(uint4*)&Ws_hi[buf][kp][c4*4] = wh[t];
            *(uint4*)&Ws_lo[buf][kp][c4*4] = wl[t];
        }
    };

    stage(0);
    __syncthreads();

    const int nk = K / KT;
    for (int kt = 0; kt < nk; kt++) {
        const int buf = kt & 1;
        if (kt + 1 < nk) {
            int k0 = (kt + 1) * KT;
            #pragma unroll
            for (int t = 0; t < NLA; t++) {
                int id = tid + t*THREADS, r = id >> 2, kq = id & 3;
                av[t] = *(const float4*)(A + (size_t)(bm + r)*K + k0 + kq*4);
            }
            int kp0 = (kt + 1) * 8;
            #pragma unroll
            for (int t = 0; t < WU; t++) {
                int u = tid + t*THREADS, kp = u / C4, c4 = u % C4;
                size_t base = (size_t)(kp0 + kp)*Nw + bn + c4*4;
                wh[t] = *(const uint4*)(Whi + base);
                wl[t] = *(const uint4*)(Wlo + base);
            }
        }

        uint32_t ah[MT][4], al[MT][4];
        #pragma unroll
        for (int mt = 0; mt < MT; mt++) {
            int m = wrow*WM + mt*16 + gr;
            ah[mt][0] = As_hi[buf][ct  ][m];
            ah[mt][1] = As_hi[buf][ct  ][m + 8];
            ah[mt][2] = As_hi[buf][ct+4][m];
            ah[mt][3] = As_hi[buf][ct+4][m + 8];
            al[mt][0] = As_lo[buf][ct  ][m];
            al[mt][1] = As_lo[buf][ct  ][m + 8];
            al[mt][2] = As_lo[buf][ct+4][m];
            al[mt][3] = As_lo[buf][ct+4][m + 8];
        }
        #pragma unroll
        for (int nt = 0; nt < NT; nt++) {
            int n = wcol*WN + nt*8 + gr;
            uint32_t bh0 = Ws_hi[buf][ct  ][n];
            uint32_t bh1 = Ws_hi[buf][ct+4][n];
            uint32_t bl0 = Ws_lo[buf][ct  ][n];
            uint32_t bl1 = Ws_lo[buf][ct+4][n];
            #pragma unroll
            for (int mt = 0; mt < MT; mt++) {
                mma_bf16(acc[mt][nt], al[mt], bh0, bh1);   // lo*hi
                mma_bf16(acc[mt][nt], ah[mt], bl0, bl1);   // hi*lo
                mma_bf16(acc[mt][nt], ah[mt], bh0, bh1);   // hi*hi
            }
        }

        if (kt + 1 < nk) stage(buf ^ 1);
        __syncthreads();
    }

    // epilogue: C-frag m16n8: c0,c1 at (gr, ct*2..+1), c2,c3 at (gr+8, same)
    #pragma unroll
    for (int mt = 0; mt < MT; mt++) {
        int row = bm + wrow*WM + mt*16 + gr;
        #pragma unroll
        for (int nt = 0; nt < NT; nt++) {
            int col = bn + wcol*WN + nt*8 + ct*2;
            float b0 = bias[col], b1 = bias[col + 1];
            float c0 = acc[mt][nt][0] + b0;
            float c1 = acc[mt][nt][1] + b1;
            float c2 = acc[mt][nt][2] + b0;
            float c3 = acc[mt][nt][3] + b1;
            if (EPI == 1) {
                c0 = gelu_exact(c0); c1 = gelu_exact(c1);
                c2 = gelu_exact(c2); c3 = gelu_exact(c3);
            }
            if (EPI == 2) {
                float2 r0 = *(const float2*)(res + (size_t)row*N + col);
                float2 r1 = *(const float2*)(res + (size_t)(row + 8)*N + col);
                c0 += r0.x; c1 += r0.y; c2 += r1.x; c3 += r1.y;
            }
            *(float2*)(C + (size_t)row*N + col)       = make_float2(c0, c1);
            *(float2*)(C + (size_t)(row + 8)*N + col) = make_float2(c2, c3);
        }
    }
}

// ---------------- attention: split-K with in-warp merge ---------------------
// grid = B*NH*2 (query halves), 256 threads. Thread pair (2q, 2q+1) handles
// the SAME query over key halves [0,128) / [128,256); partial online-softmax
// states merge via shfl_xor(1) (partner always in-warp).
__global__ void attention_kernel(const float* __restrict__ qkv,
                                 float* __restrict__ outp) {
    __shared__ float Ks[S_][DH_];
    int bid  = blockIdx.x;
    int half = bid & 1;
    int bh   = bid >> 1;
    int b    = bh >> 3, h = bh & 7;
    int tid  = threadIdx.x;                 // 0..255
    const float* base = qkv + (size_t)b*S_*(3*H_);
    {
        const float4* kr = (const float4*)(base + (size_t)tid*(3*H_) + H_ + h*DH_);
        float4* dst = (float4*)&Ks[tid][0];
        #pragma unroll
        for (int i = 0; i < DH_/4; i++) dst[i] = kr[i];
    }
    int qlocal = tid >> 1;                  // 0..127
    int ks     = tid & 1;                   // key half
    int qrow   = half*128 + qlocal;
    float q[DH_];
    {
        const float4* qr = (const float4*)(base + (size_t)qrow*(3*H_) + h*DH_);
        #pragma unroll
        for (int i = 0; i < DH_/4; i++) ((float4*)q)[i] = qr[i];
    }
    __syncthreads();

    const float scale = 0.17677669529663688110f;   // 1/sqrt(32)
    float m = -INFINITY, l = 0.f;
    float acc[DH_];
    #pragma unroll
    for (int d = 0; d < DH_; d++) acc[d] = 0.f;
    const float* vbase = base + 2*H_ + h*DH_;
    const int j0 = ks * 128;

    for (int jj = 0; jj < 128; jj += 2) {
        int j = j0 + jj;
        float d0 = 0.f, d1 = 0.f, d2 = 0.f, d3 = 0.f;
        float e0 = 0.f, e1 = 0.f, e2 = 0.f, e3 = 0.f;
        #pragma unroll
        for (int i = 0; i < DH_/4; i++) {
            float4 k0 = ((const float4*)&Ks[j][0])[i];
            float4 k1 = ((const float4*)&Ks[j+1][0])[i];
            d0 = fmaf(q[4*i+0], k0.x, d0);
            d1 = fmaf(q[4*i+1], k0.y, d1);
            d2 = fmaf(q[4*i+2], k0.z, d2);
            d3 = fmaf(q[4*i+3], k0.w, d3);
            e0 = fmaf(q[4*i+0], k1.x, e0);
            e1 = fmaf(q[4*i+1], k1.y, e1);
            e2 = fmaf(q[4*i+2], k1.z, e2);
            e3 = fmaf(q[4*i+3], k1.w, e3);
        }
        float s0 = ((d0 + d1) + (d2 + d3)) * scale;
        float s1 = ((e0 + e1) + (e2 + e3)) * scale;
        float mn = fmaxf(m, fmaxf(s0, s1));
        float c  = __expf(m - mn);
        float p0 = __expf(s0 - mn);
        float p1 = __expf(s1 - mn);
        l = l*c + p0 + p1;
        const float4* v0 = (const float4*)(vbase + (size_t)j*(3*H_));
        const float4* v1 = (const float4*)(vbase + (size_t)(j+1)*(3*H_));
        #pragma unroll
        for (int i = 0; i < DH_/4; i++) {
            float4 a = v0[i], bq = v1[i];
            acc[i*4+0] = fmaf(acc[i*4+0], c, fmaf(p0, a.x, p1*bq.x));
            acc[i*4+1] = fmaf(acc[i*4+1], c, fmaf(p0, a.y, p1*bq.y));
            acc[i*4+2] = fmaf(acc[i*4+2], c, fmaf(p0, a.z, p1*bq.z));
            acc[i*4+3] = fmaf(acc[i*4+3], c, fmaf(p0, a.w, p1*bq.w));
        }
        m = mn;
    }

    // merge partial softmax state with partner lane (other key half)
    float mo = __shfl_xor_sync(0xffffffffu, m, 1);
    float lo = __shfl_xor_sync(0xffffffffu, l, 1);
    float mn = fmaxf(m, mo);
    float c1 = __expf(m  - mn);
    float c2 = __expf(mo - mn);
    float ltot = l*c1 + lo*c2;
    float inv = 1.0f / ltot;
    #pragma unroll
    for (int d = 0; d < DH_; d++) {
        float ao = __shfl_xor_sync(0xffffffffu, acc[d], 1);
        acc[d] = (acc[d]*c1 + ao*c2) * inv;
    }
    // both lanes hold the full result; each writes half (4 float4 each)
    float* orow = outp + (size_t)(b*S_ + qrow)*H_ + h*DH_ + ks*16;
    #pragma unroll
    for (int i = 0; i < 4; i++)
        ((float4*)orow)[i] = ((float4*)&acc[ks*16])[i];
}

// ---------------- layernorm: warp-per-row, barrier-free ----------
__global__ void layernorm_kernel(const float* __restrict__ in,
                                 const float* __restrict__ gw,
                                 const float* __restrict__ gb,
                                 float* __restrict__ outp) {
    int warp = threadIdx.x >> 5;
    int lane = threadIdx.x & 31;
    int row  = blockIdx.x * 8 + warp;
    const float4* in4 = (const float4*)in;
    float4 a = in4[(size_t)row*64 + lane*2];
    float4 b = in4[(size_t)row*64 + lane*2 + 1];
    float s1 = ((a.x + a.y) + (a.z + a.w)) + ((b.x + b.y) + (b.z + b.w));
    float s2 = ((a.x*a.x + a.y*a.y) + (a.z*a.z + a.w*a.w))
             + ((b.x*b.x + b.y*b.y) + (b.z*b.z + b.w*b.w));
    #pragma unroll
    for (int o = 16; o > 0; o >>= 1) {
        s1 += __shfl_xor_sync(0xffffffffu, s1, o);
        s2 += __shfl_xor_sync(0xffffffffu, s2, o);
    }
    float mean = s1 * (1.0f/H_);
    float var  = s2 * (1.0f/H_) - mean*mean;
    float rstd = rsqrtf(var + 1e-5f);
    float4 g0 = ((const float4*)gw)[lane*2];
    float4 g1 = ((const float4*)gw)[lane*2 + 1];
    float4 o0 = ((const float4*)gb)[lane*2];
    float4 o1 = ((const float4*)gb)[lane*2 + 1];
    float4 r0, r1;
    r0.x = (a.x - mean)*rstd*g0.x + o0.x;
    r0.y = (a.y - mean)*rstd*g0.y + o0.y;
    r0.z = (a.z - mean)*rstd*g0.z + o0.z;
    r0.w = (a.w - mean)*rstd*g0.w + o0.w;
    r1.x = (b.x - mean)*rstd*g1.x + o1.x;
    r1.y = (b.y - mean)*rstd*g1.y + o1.y;
    r1.z = (b.z - mean)*rstd*g1.z + o1.z;
    r1.w = (b.w - mean)*rstd*g1.w + o1.w;
    ((float4*)outp)[(size_t)row*64 + lane*2]     = r0;
    ((float4*)outp)[(size_t)row*64 + lane*2 + 1] = r1;
}

// ---------------- head2: logits (M x 13), one thread per output ----------
__global__ void head2_kernel(const float* __restrict__ X,
                             const float* __restrict__ W,
                             const float* __restrict__ bias) {
    int t = blockIdx.x * blockDim.x + threadIdx.x;
    if (t >= B_*S_*NC_) return;
    int row = t / NC_, c = t - row*NC_;
    const float4* x = (const float4*)(X + (size_t)row*H_);
    const float4* w = (const float4*)(W + (size_t)c*H_);
    float s0 = 0.f, s1 = 0.f, s2 = 0.f, s3 = 0.f;
    #pragma unroll 8
    for (int k = 0; k < H_/4; k++) {
        float4 xv = x[k], wv = w[k];
        s0 = fmaf(xv.x, wv.x, s0); s1 = fmaf(xv.y, wv.y, s1);
        s2 = fmaf(xv.z, wv.z, s2); s3 = fmaf(xv.w, wv.w, s3);
    }
    g_logits[t] = (s0+s1) + (s2+s3) + bias[c];
}

// ---------------- final gather to point logits ----------
__global__ void gather_kernel(float* __restrict__ out) {
    int t = blockIdx.x * blockDim.x + threadIdx.x;
    if (t >= B_*N_*NC_) return;
    int r = t / NC_;
    int c = t - r*NC_;
    int b = r >> 15;                // r / N_
    int a = g_assign[r];
    out[t] = g_logits[(b*S_ + a)*NC_ + c];
}

// ---------------- host launcher ----------
extern "C" void kernel_launch(void* const* d_in, const int* in_sizes, int n_in,
                              void* d_out, int out_size) {
    const float* xyz      = (const float*)d_in[0];
    const float* feat     = (const float*)d_in[1];
    const int*   seed_idx = (const int*)  d_in[2];
    const float* proj_w   = (const float*)d_in[3];
    const float* proj_b   = (const float*)d_in[4];
    const float* qkv_w    = (const float*)d_in[5];
    const float* qkv_b    = (const float*)d_in[6];
    const float* out_w    = (const float*)d_in[7];
    const float* out_b    = (const float*)d_in[8];
    const float* ln1_g    = (const float*)d_in[9];
    const float* ln1_b    = (const float*)d_in[10];
    const float* ln2_g    = (const float*)d_in[11];
    const float* ln2_b    = (const float*)d_in[12];
    const float* ff1_w    = (const float*)d_in[13];
    const float* ff1_b    = (const float*)d_in[14];
    const float* ff2_w    = (const float*)d_in[15];
    const float* ff2_b    = (const float*)d_in[16];
    const float* hln_g    = (const float*)d_in[17];
    const float* hln_b    = (const float*)d_in[18];
    const float* h1_w     = (const float*)d_in[19];
    const float* h1_b     = (const float*)d_in[20];
    const float* h2_w     = (const float*)d_in[21];
    const float* h2_b     = (const float*)d_in[22];
    float* out = (float*)d_out;

    float *p_x, *p_qkv, *p_attn, *p_tmp, *p_ff, *p_h1;
    uint32_t *p_Whi, *p_Wlo;
    cudaGetSymbolAddress((void**)&p_x,    g_x);
    cudaGetSymbolAddress((void**)&p_qkv,  g_qkv);
    cudaGetSymbolAddress((void**)&p_attn, g_attn);
    cudaGetSymbolAddress((void**)&p_tmp,  g_tmp);
    cudaGetSymbolAddress((void**)&p_ff,   g_ff);
    cudaGetSymbolAddress((void**)&p_h1,   g_h1);
    cudaGetSymbolAddress((void**)&p_Whi,  g_Whi);
    cudaGetSymbolAddress((void**)&p_Wlo,  g_Wlo);

    const int M = B_*S_;   // 4096

    split_all_kernel<<<(W_TOTAL + 255)/256, 256>>>(qkv_w, out_w, ff1_w,
                                                   ff2_w, h1_w);
    assign_kernel<<<B_*16, 256>>>(xyz, feat, seed_idx);
    tokens_kernel<<<M/8, 256>>>(xyz, seed_idx, proj_w, proj_b);

    for (int l = 0; l < 2; l++) {
        // QKV: M=4096, N=768, K=256 -> 64x128 tiles, grid 6x64=384
        sgemm_tc<64,128,64,32,128,4,0><<<dim3(3*H_/128, M/64), 128>>>(
            p_x, p_Whi+OFF_QKV + l*98304, p_Wlo+OFF_QKV + l*98304,
            qkv_b + l*3*H_, nullptr, p_qkv, M, 3*H_, H_, 768);
        attention_kernel<<<B_*NH_*2, 256>>>(p_qkv, p_attn);
        // out-proj: N=256, K=256 -> 64x64 tiles, grid 4x64=256, +residual
        sgemm_tc<64,64,32,32,128,4,2><<<dim3(H_/64, M/64), 128>>>(
            p_attn, p_Whi+OFF_OUT + l*32768, p_Wlo+OFF_OUT + l*32768,
            out_b + l*H_, p_x, p_tmp, M, H_, H_, 256);
        layernorm_kernel<<<M/8, 256>>>(p_tmp, ln1_g + l*H_, ln1_b + l*H_, p_x);
        // FF1: N=1024, K=256 -> 64x128 tiles, grid 8x64=512, gelu
        sgemm_tc<64,128,64,32,128,4,1><<<dim3(DFF_/128, M/64), 128>>>(
            p_x, p_Whi+OFF_FF1 + l*131072, p_Wlo+OFF_FF1 + l*131072,
            ff1_b + l*DFF_, nullptr, p_ff, M, DFF_, H_, 1024);
        // FF2: N=256, K=1024 -> 64x64 tiles, +residual
        sgemm_tc<64,64,32,32,128,4,2><<<dim3(H_/64, M/64), 128>>>(
            p_ff, p_Whi+OFF_FF2 + l*131072, p_Wlo+OFF_FF2 + l*131072,
            ff2_b + l*H_, p_x, p_tmp, M, H_, DFF_, 256);
        layernorm_kernel<<<M/8, 256>>>(p_tmp, ln2_g + l*H_, ln2_b + l*H_, p_x);
    }

    layernorm_kernel<<<M/8, 256>>>(p_x, hln_g, hln_b, p_tmp);
    sgemm_tc<64,64,32,32,128,4,1><<<dim3(H_/64, M/64), 128>>>(
        p_tmp, p_Whi+OFF_H1, p_Wlo+OFF_H1, h1_b, nullptr, p_h1,
        M, H_, H_, 256);
    head2_kernel<<<(M*NC_ + 255)/256, 256>>>(p_h1, h2_w, h2_b);
    gather_kernel<<<(B_*N_*NC_ + 255)/256, 256>>>(out);
}